// round 1
// baseline (speedup 1.0000x reference)
#include <cuda_runtime.h>
#include <math.h>

#define NROIS 1000
#define NCH   192
#define POOLS 7
#define KDIM  (NCH * POOLS * POOLS)   // 9408
#define DDIM  768
#define SPLITK 4

// ---- scratch (static device globals; no allocation) ----
__device__ float g_pooled[NROIS * KDIM];            // 37.6 MB
__device__ float g_part[SPLITK * NROIS * DDIM];     // 12.3 MB
__device__ float g_x1[NROIS * DDIM];
__device__ float g_x2[NROIS * DDIM];

// ============================================================
// Kernel 1: pyramid RoIAlign -> pooled [NROIS, 192, 7, 7]
// one block per ROI, 192 threads (one per channel)
// ============================================================
__global__ void roi_align_kernel(const float* __restrict__ f0,
                                 const float* __restrict__ f1,
                                 const float* __restrict__ f2,
                                 const float* __restrict__ f3,
                                 const float* __restrict__ rois,
                                 float* __restrict__ pooled)
{
    const int r = blockIdx.x;
    const int tid = threadIdx.x;

    __shared__ int   sIdx[196][4];
    __shared__ float sW[196][4];

    const float* roi = rois + r * 5;
    const float by1 = roi[0], bx1 = roi[1], by2 = roi[2], bx2 = roi[3];
    const int bix = (int)roi[4];

    const float h = by2 - by1;
    const float w = bx2 - bx1;
    float area = h * w;
    int lvl;
    if (area > 0.0f) {
        float lv = 4.0f + 0.5f * log2f(area);
        lvl = (int)rintf(lv);
        lvl = max(0, min(3, lvl));
    } else {
        lvl = 0;
    }

    const float* fm;
    int H;
    if      (lvl == 0) { fm = f0; H = 128; }
    else if (lvl == 1) { fm = f1; H = 64;  }
    else if (lvl == 2) { fm = f2; H = 32;  }
    else               { fm = f3; H = 16;  }
    const int W = H;
    const float Hs = (float)H;

    const float y1s = by1 * Hs, x1s = bx1 * Hs;
    const float y2s = by2 * Hs, x2s = bx2 * Hs;
    const float bin_h = fmaxf(y2s - y1s, 1.0f) * (1.0f / (float)POOLS);
    const float bin_w = fmaxf(x2s - x1s, 1.0f) * (1.0f / (float)POOLS);

    // precompute the 14x14 sample positions (indices + bilinear weights)
    for (int s = tid; s < 196; s += blockDim.x) {
        const int jy = s / 14, jx = s % 14;
        const float gy = (float)(jy >> 1) + 0.25f + (float)(jy & 1) * 0.5f;
        const float gx = (float)(jx >> 1) + 0.25f + (float)(jx & 1) * 0.5f;
        float y = y1s + gy * bin_h;
        float x = x1s + gx * bin_w;
        const bool valid = (y >= -1.0f) && (y <= Hs) && (x >= -1.0f) && (x <= Hs);
        y = fminf(fmaxf(y, 0.0f), Hs - 1.0f);
        x = fminf(fmaxf(x, 0.0f), Hs - 1.0f);
        const float yf = floorf(y), xf = floorf(x);
        const int y0 = (int)yf, x0 = (int)xf;
        const int y1i = min(y0 + 1, H - 1);
        const int x1i = min(x0 + 1, W - 1);
        const float ly = y - yf, lx = x - xf;
        const float v = valid ? 1.0f : 0.0f;
        sIdx[s][0] = y0 * W + x0;
        sIdx[s][1] = y0 * W + x1i;
        sIdx[s][2] = y1i * W + x0;
        sIdx[s][3] = y1i * W + x1i;
        sW[s][0] = (1.0f - ly) * (1.0f - lx) * v;
        sW[s][1] = (1.0f - ly) * lx * v;
        sW[s][2] = ly * (1.0f - lx) * v;
        sW[s][3] = ly * lx * v;
    }
    __syncthreads();

    const int c = tid;
    if (c < NCH) {
        const float* plane = fm + ((size_t)bix * NCH + c) * (size_t)(H * W);
        float* outp = pooled + ((size_t)r * NCH + c) * 49;
        #pragma unroll
        for (int ph = 0; ph < 7; ph++) {
            #pragma unroll
            for (int pw = 0; pw < 7; pw++) {
                float acc = 0.0f;
                #pragma unroll
                for (int sy = 0; sy < 2; sy++) {
                    #pragma unroll
                    for (int sx = 0; sx < 2; sx++) {
                        const int s = (ph * 2 + sy) * 14 + (pw * 2 + sx);
                        acc += sW[s][0] * __ldg(plane + sIdx[s][0])
                             + sW[s][1] * __ldg(plane + sIdx[s][1])
                             + sW[s][2] * __ldg(plane + sIdx[s][2])
                             + sW[s][3] * __ldg(plane + sIdx[s][3]);
                    }
                }
                outp[ph * 7 + pw] = acc * 0.25f;
            }
        }
    }
}

// ============================================================
// Kernel 2: split-K GEMM_NT partial:  Cpart[kz] += A[M,K] * B[N,K]^T
// BM=BN=128, BK=8, TM=TN=8, 256 threads. grid (ceil(M/128), N/128, SPLITK)
// ============================================================
__global__ void __launch_bounds__(256, 2)
gemm_nt_splitk(const float* __restrict__ A, const float* __restrict__ B,
               float* __restrict__ Cpart, int M, int N, int K)
{
    const int BM = 128, BN = 128, BK = 8;
    __shared__ float As[BK][BM];
    __shared__ float Bs[BK][BN];

    const int tid = threadIdx.x;
    const int tx = tid & 15;        // 0..15 -> N microtile
    const int ty = tid >> 4;        // 0..15 -> M microtile
    const int bm = blockIdx.x * BM;
    const int bn = blockIdx.y * BN;
    const int kz = blockIdx.z;
    const int Kspl = K / SPLITK;
    const int k0 = kz * Kspl;

    float acc[8][8];
    #pragma unroll
    for (int i = 0; i < 8; i++)
        #pragma unroll
        for (int j = 0; j < 8; j++) acc[i][j] = 0.0f;

    const int lrow = tid >> 1;           // 0..127
    const int lk   = (tid & 1) * 4;      // 0 or 4
    const float* Aptr = A + (size_t)(bm + lrow) * K + k0 + lk;
    const float* Bptr = B + (size_t)(bn + lrow) * K + k0 + lk;
    const bool aValid = (bm + lrow) < M;   // N side always full (768 % 128 == 0)

    for (int kt = 0; kt < Kspl; kt += BK) {
        float4 av = aValid ? *(const float4*)Aptr : make_float4(0.f, 0.f, 0.f, 0.f);
        float4 bv = *(const float4*)Bptr;
        As[lk + 0][lrow] = av.x; As[lk + 1][lrow] = av.y;
        As[lk + 2][lrow] = av.z; As[lk + 3][lrow] = av.w;
        Bs[lk + 0][lrow] = bv.x; Bs[lk + 1][lrow] = bv.y;
        Bs[lk + 2][lrow] = bv.z; Bs[lk + 3][lrow] = bv.w;
        __syncthreads();

        #pragma unroll
        for (int kk = 0; kk < BK; kk++) {
            float a[8], b[8];
            *(float4*)(a)     = *(const float4*)&As[kk][ty * 8];
            *(float4*)(a + 4) = *(const float4*)&As[kk][ty * 8 + 4];
            *(float4*)(b)     = *(const float4*)&Bs[kk][tx * 8];
            *(float4*)(b + 4) = *(const float4*)&Bs[kk][tx * 8 + 4];
            #pragma unroll
            for (int i = 0; i < 8; i++)
                #pragma unroll
                for (int j = 0; j < 8; j++)
                    acc[i][j] = fmaf(a[i], b[j], acc[i][j]);
        }
        __syncthreads();
        Aptr += BK;
        Bptr += BK;
    }

    float* Cp = Cpart + (size_t)kz * M * N;
    #pragma unroll
    for (int i = 0; i < 8; i++) {
        const int m = bm + ty * 8 + i;
        if (m < M) {
            float4* o = (float4*)&Cp[(size_t)m * N + bn + tx * 8];
            o[0] = make_float4(acc[i][0], acc[i][1], acc[i][2], acc[i][3]);
            o[1] = make_float4(acc[i][4], acc[i][5], acc[i][6], acc[i][7]);
        }
    }
}

// ============================================================
// Kernel 3: reduce split-K partials + bias + relu
// ============================================================
__global__ void reduce_bias_relu(const float* __restrict__ part,
                                 const float* __restrict__ bias,
                                 float* __restrict__ out, int M, int N)
{
    const int i = blockIdx.x * blockDim.x + threadIdx.x;
    if (i < M * N) {
        float s = bias[i % N];
        #pragma unroll
        for (int kz = 0; kz < SPLITK; kz++)
            s += part[(size_t)kz * M * N + i];
        out[i] = fmaxf(s, 0.0f);
    }
}

// ============================================================
// Kernel 4: heads -- 14 outputs per roi, scatter-packed into d_out
// ============================================================
__global__ void heads_kernel(const float* __restrict__ x,
                             const float* __restrict__ wb, const float* __restrict__ bb,
                             const float* __restrict__ wc, const float* __restrict__ bc,
                             const float* __restrict__ wr, const float* __restrict__ br,
                             const float* __restrict__ wu, const float* __restrict__ bu,
                             float* __restrict__ out)
{
    const int g = blockIdx.x * blockDim.x + threadIdx.x;
    if (g >= NROIS * 14) return;
    const int r = g / 14;
    const int o = g % 14;

    const float* wrow;
    float acc;
    if (o < 8)       { wrow = wb + o * DDIM;        acc = bb[o]; }
    else if (o < 10) { wrow = wc + (o - 8) * DDIM;  acc = bc[o - 8]; }
    else if (o < 12) { wrow = wr + (o - 10) * DDIM; acc = br[o - 10]; }
    else             { wrow = wu + (o - 12) * DDIM; acc = bu[o - 12]; }

    const float* xr = x + (size_t)r * DDIM;
    #pragma unroll 4
    for (int k = 0; k < DDIM; k += 4) {
        float4 xv = *(const float4*)(xr + k);
        float4 wv = __ldg((const float4*)(wrow + k));
        acc = fmaf(xv.x, wv.x, acc);
        acc = fmaf(xv.y, wv.y, acc);
        acc = fmaf(xv.z, wv.z, acc);
        acc = fmaf(xv.w, wv.w, acc);
    }

    if (o < 8)       out[r * 8 + o] = acc;                             // bbox [1000,2,4]
    else if (o < 10) out[8000 + r * 2 + (o - 8)] = acc;                // logits [1000,2]
    else if (o < 12) out[10000 + r * 4 + (o - 10) * 2] = acc;          // regress[...,0]
    else             out[10000 + r * 4 + (o - 12) * 2 + 1] = acc;      // regress[...,1]
}

// ============================================================
// launch
// ============================================================
extern "C" void kernel_launch(void* const* d_in, const int* in_sizes, int n_in,
                              void* d_out, int out_size)
{
    const float* fmap0 = (const float*)d_in[0];
    const float* fmap1 = (const float*)d_in[1];
    const float* fmap2 = (const float*)d_in[2];
    const float* fmap3 = (const float*)d_in[3];
    const float* rois  = (const float*)d_in[4];
    const float* w1    = (const float*)d_in[5];
    const float* b1    = (const float*)d_in[6];
    const float* w2    = (const float*)d_in[7];
    const float* b2    = (const float*)d_in[8];
    const float* w_bbox = (const float*)d_in[9];
    const float* b_bbox = (const float*)d_in[10];
    const float* w_cls  = (const float*)d_in[11];
    const float* b_cls  = (const float*)d_in[12];
    const float* w_reg  = (const float*)d_in[13];
    const float* b_reg  = (const float*)d_in[14];
    const float* w_unc  = (const float*)d_in[15];
    const float* b_unc  = (const float*)d_in[16];
    float* out = (float*)d_out;

    float *p_pooled, *p_part, *p_x1, *p_x2;
    cudaGetSymbolAddress((void**)&p_pooled, g_pooled);
    cudaGetSymbolAddress((void**)&p_part,   g_part);
    cudaGetSymbolAddress((void**)&p_x1,     g_x1);
    cudaGetSymbolAddress((void**)&p_x2,     g_x2);

    // 1. RoIAlign
    roi_align_kernel<<<NROIS, NCH>>>(fmap0, fmap1, fmap2, fmap3, rois, p_pooled);

    // 2. GEMM1: pooled[1000,9408] x w1[768,9408]^T  (split-K partials)
    {
        dim3 grid((NROIS + 127) / 128, DDIM / 128, SPLITK);
        gemm_nt_splitk<<<grid, 256>>>(p_pooled, w1, p_part, NROIS, DDIM, KDIM);
        reduce_bias_relu<<<(NROIS * DDIM + 255) / 256, 256>>>(p_part, b1, p_x1, NROIS, DDIM);
    }

    // 3. GEMM2: x1[1000,768] x w2[768,768]^T
    {
        dim3 grid((NROIS + 127) / 128, DDIM / 128, SPLITK);
        gemm_nt_splitk<<<grid, 256>>>(p_x1, w2, p_part, NROIS, DDIM, DDIM);
        reduce_bias_relu<<<(NROIS * DDIM + 255) / 256, 256>>>(p_part, b2, p_x2, NROIS, DDIM);
    }

    // 4. heads
    heads_kernel<<<(NROIS * 14 + 255) / 256, 256>>>(
        p_x2, w_bbox, b_bbox, w_cls, b_cls, w_reg, b_reg, w_unc, b_unc, out);
}

// round 2
// speedup vs baseline: 2.3628x; 2.3628x over previous
#include <cuda_runtime.h>
#include <math.h>

#define NROIS 1000
#define NCH   192
#define POOLS 7
#define KDIM  (NCH * POOLS * POOLS)   // 9408
#define DDIM  768
#define SPLITK 6

// per-level spatial sizes
#define HW0 (128*128)
#define HW1 (64*64)
#define HW2 (32*32)
#define HW3 (16*16)
#define B_  4

// ---- scratch (static device globals; no allocation) ----
__device__ float g_fT0[B_ * HW0 * NCH];
__device__ float g_fT1[B_ * HW1 * NCH];
__device__ float g_fT2[B_ * HW2 * NCH];
__device__ float g_fT3[B_ * HW3 * NCH];
__device__ float g_pooled[NROIS * KDIM];
__device__ float g_part[SPLITK * NROIS * DDIM];
__device__ float g_x1[NROIS * DDIM];
__device__ float g_x2[NROIS * DDIM];

// ============================================================
// Kernel 0: transpose [B,C,HW] -> [B,HW,C]  (32x32 tiles)
// grid (HW/32, C/32, B), block (32,8)
// ============================================================
__global__ void transpose_kernel(const float* __restrict__ in,
                                 float* __restrict__ out, int HW)
{
    __shared__ float tile[32][33];
    const int p0 = blockIdx.x * 32;
    const int c0 = blockIdx.y * 32;
    const int b  = blockIdx.z;
    const int tx = threadIdx.x, ty = threadIdx.y;

    #pragma unroll
    for (int j = 0; j < 4; j++) {
        const int c = c0 + ty + j * 8;
        tile[ty + j * 8][tx] = in[((size_t)b * NCH + c) * HW + p0 + tx];
    }
    __syncthreads();
    #pragma unroll
    for (int j = 0; j < 4; j++) {
        const int p = p0 + ty + j * 8;
        out[((size_t)b * HW + p) * NCH + c0 + tx] = tile[tx][ty + j * 8];
    }
}

// ============================================================
// Kernel 1: pyramid RoIAlign over channel-last fmaps
// one block per ROI, 192 threads (one per channel), coalesced gathers
// ============================================================
__global__ void roi_align_kernel(const float* __restrict__ fT0,
                                 const float* __restrict__ fT1,
                                 const float* __restrict__ fT2,
                                 const float* __restrict__ fT3,
                                 const float* __restrict__ rois,
                                 float* __restrict__ pooled)
{
    const int r = blockIdx.x;
    const int tid = threadIdx.x;

    __shared__ int   sIdx[196][4];     // pixel index pre-multiplied by NCH
    __shared__ float sW[196][4];
    __shared__ float sBuf[NCH * 49];   // pooled staging [c][bin]

    const float* roi = rois + r * 5;
    const float by1 = roi[0], bx1 = roi[1], by2 = roi[2], bx2 = roi[3];
    const int bix = (int)roi[4];

    const float h = by2 - by1;
    const float w = bx2 - bx1;
    const float area = h * w;
    int lvl;
    if (area > 0.0f) {
        float lv = 4.0f + 0.5f * log2f(area);
        lvl = (int)rintf(lv);
        lvl = max(0, min(3, lvl));
    } else {
        lvl = 0;
    }

    const float* fm;
    int H;
    if      (lvl == 0) { fm = fT0; H = 128; }
    else if (lvl == 1) { fm = fT1; H = 64;  }
    else if (lvl == 2) { fm = fT2; H = 32;  }
    else               { fm = fT3; H = 16;  }
    const int W = H;
    const float Hs = (float)H;

    const float y1s = by1 * Hs, x1s = bx1 * Hs;
    const float y2s = by2 * Hs, x2s = bx2 * Hs;
    const float bin_h = fmaxf(y2s - y1s, 1.0f) * (1.0f / (float)POOLS);
    const float bin_w = fmaxf(x2s - x1s, 1.0f) * (1.0f / (float)POOLS);

    for (int s = tid; s < 196; s += blockDim.x) {
        const int jy = s / 14, jx = s % 14;
        const float gy = (float)(jy >> 1) + 0.25f + (float)(jy & 1) * 0.5f;
        const float gx = (float)(jx >> 1) + 0.25f + (float)(jx & 1) * 0.5f;
        float y = y1s + gy * bin_h;
        float x = x1s + gx * bin_w;
        const bool valid = (y >= -1.0f) && (y <= Hs) && (x >= -1.0f) && (x <= Hs);
        y = fminf(fmaxf(y, 0.0f), Hs - 1.0f);
        x = fminf(fmaxf(x, 0.0f), Hs - 1.0f);
        const float yf = floorf(y), xf = floorf(x);
        const int y0 = (int)yf, x0 = (int)xf;
        const int y1i = min(y0 + 1, H - 1);
        const int x1i = min(x0 + 1, W - 1);
        const float ly = y - yf, lx = x - xf;
        const float v = valid ? 1.0f : 0.0f;
        sIdx[s][0] = (y0 * W + x0) * NCH;
        sIdx[s][1] = (y0 * W + x1i) * NCH;
        sIdx[s][2] = (y1i * W + x0) * NCH;
        sIdx[s][3] = (y1i * W + x1i) * NCH;
        sW[s][0] = (1.0f - ly) * (1.0f - lx) * v;
        sW[s][1] = (1.0f - ly) * lx * v;
        sW[s][2] = ly * (1.0f - lx) * v;
        sW[s][3] = ly * lx * v;
    }
    __syncthreads();

    // lanes = consecutive channels -> every gather is a coalesced 768B warp read
    const int c = tid;  // 0..191
    const float* base = fm + (size_t)bix * (H * W) * NCH + c;
    #pragma unroll
    for (int ph = 0; ph < 7; ph++) {
        for (int pw = 0; pw < 7; pw++) {
            float acc = 0.0f;
            #pragma unroll
            for (int sy = 0; sy < 2; sy++) {
                #pragma unroll
                for (int sx = 0; sx < 2; sx++) {
                    const int s = (ph * 2 + sy) * 14 + (pw * 2 + sx);
                    acc += sW[s][0] * __ldg(base + sIdx[s][0])
                         + sW[s][1] * __ldg(base + sIdx[s][1])
                         + sW[s][2] * __ldg(base + sIdx[s][2])
                         + sW[s][3] * __ldg(base + sIdx[s][3]);
                }
            }
            sBuf[c * 49 + ph * 7 + pw] = acc * 0.25f;  // gcd(49,32)=1 -> conflict-free
        }
    }
    __syncthreads();

    // coalesced write-out: pooled row layout is exactly [c][bin]
    float* outp = pooled + (size_t)r * KDIM;
    for (int i = tid; i < KDIM; i += NCH)
        outp[i] = sBuf[i];
}

// ============================================================
// Kernel 2: split-K GEMM_NT partial:  Cpart[kz] = A[M,K] * B[N,K]^T slice
// BM=BN=128, BK=8, TM=TN=8, 256 threads. grid (ceil(M/128), N/128, SPLITK)
// ============================================================
__global__ void __launch_bounds__(256, 2)
gemm_nt_splitk(const float* __restrict__ A, const float* __restrict__ B,
               float* __restrict__ Cpart, int M, int N, int K)
{
    const int BM = 128, BN = 128, BK = 8;
    __shared__ float As[BK][BM];
    __shared__ float Bs[BK][BN];

    const int tid = threadIdx.x;
    const int tx = tid & 15;
    const int ty = tid >> 4;
    const int bm = blockIdx.x * BM;
    const int bn = blockIdx.y * BN;
    const int kz = blockIdx.z;
    const int Kspl = K / SPLITK;
    const int k0 = kz * Kspl;

    float acc[8][8];
    #pragma unroll
    for (int i = 0; i < 8; i++)
        #pragma unroll
        for (int j = 0; j < 8; j++) acc[i][j] = 0.0f;

    const int lrow = tid >> 1;
    const int lk   = (tid & 1) * 4;
    const float* Aptr = A + (size_t)(bm + lrow) * K + k0 + lk;
    const float* Bptr = B + (size_t)(bn + lrow) * K + k0 + lk;
    const bool aValid = (bm + lrow) < M;

    for (int kt = 0; kt < Kspl; kt += BK) {
        float4 av = aValid ? *(const float4*)Aptr : make_float4(0.f, 0.f, 0.f, 0.f);
        float4 bv = *(const float4*)Bptr;
        As[lk + 0][lrow] = av.x; As[lk + 1][lrow] = av.y;
        As[lk + 2][lrow] = av.z; As[lk + 3][lrow] = av.w;
        Bs[lk + 0][lrow] = bv.x; Bs[lk + 1][lrow] = bv.y;
        Bs[lk + 2][lrow] = bv.z; Bs[lk + 3][lrow] = bv.w;
        __syncthreads();

        #pragma unroll
        for (int kk = 0; kk < BK; kk++) {
            float a[8], b[8];
            *(float4*)(a)     = *(const float4*)&As[kk][ty * 8];
            *(float4*)(a + 4) = *(const float4*)&As[kk][ty * 8 + 4];
            *(float4*)(b)     = *(const float4*)&Bs[kk][tx * 8];
            *(float4*)(b + 4) = *(const float4*)&Bs[kk][tx * 8 + 4];
            #pragma unroll
            for (int i = 0; i < 8; i++)
                #pragma unroll
                for (int j = 0; j < 8; j++)
                    acc[i][j] = fmaf(a[i], b[j], acc[i][j]);
        }
        __syncthreads();
        Aptr += BK;
        Bptr += BK;
    }

    float* Cp = Cpart + (size_t)kz * M * N;
    #pragma unroll
    for (int i = 0; i < 8; i++) {
        const int m = bm + ty * 8 + i;
        if (m < M) {
            float4* o = (float4*)&Cp[(size_t)m * N + bn + tx * 8];
            o[0] = make_float4(acc[i][0], acc[i][1], acc[i][2], acc[i][3]);
            o[1] = make_float4(acc[i][4], acc[i][5], acc[i][6], acc[i][7]);
        }
    }
}

// ============================================================
// Kernel 3: reduce split-K partials + bias + relu
// ============================================================
__global__ void reduce_bias_relu(const float* __restrict__ part,
                                 const float* __restrict__ bias,
                                 float* __restrict__ out, int M, int N)
{
    const int i = blockIdx.x * blockDim.x + threadIdx.x;
    if (i < M * N) {
        float s = bias[i % N];
        #pragma unroll
        for (int kz = 0; kz < SPLITK; kz++)
            s += part[(size_t)kz * M * N + i];
        out[i] = fmaxf(s, 0.0f);
    }
}

// ============================================================
// Kernel 4: heads -- 14 outputs per roi, scatter-packed into d_out
// ============================================================
__global__ void heads_kernel(const float* __restrict__ x,
                             const float* __restrict__ wb, const float* __restrict__ bb,
                             const float* __restrict__ wc, const float* __restrict__ bc,
                             const float* __restrict__ wr, const float* __restrict__ br,
                             const float* __restrict__ wu, const float* __restrict__ bu,
                             float* __restrict__ out)
{
    const int g = blockIdx.x * blockDim.x + threadIdx.x;
    if (g >= NROIS * 14) return;
    const int r = g / 14;
    const int o = g % 14;

    const float* wrow;
    float acc;
    if (o < 8)       { wrow = wb + o * DDIM;        acc = bb[o]; }
    else if (o < 10) { wrow = wc + (o - 8) * DDIM;  acc = bc[o - 8]; }
    else if (o < 12) { wrow = wr + (o - 10) * DDIM; acc = br[o - 10]; }
    else             { wrow = wu + (o - 12) * DDIM; acc = bu[o - 12]; }

    const float* xr = x + (size_t)r * DDIM;
    #pragma unroll 4
    for (int k = 0; k < DDIM; k += 4) {
        float4 xv = *(const float4*)(xr + k);
        float4 wv = __ldg((const float4*)(wrow + k));
        acc = fmaf(xv.x, wv.x, acc);
        acc = fmaf(xv.y, wv.y, acc);
        acc = fmaf(xv.z, wv.z, acc);
        acc = fmaf(xv.w, wv.w, acc);
    }

    if (o < 8)       out[r * 8 + o] = acc;
    else if (o < 10) out[8000 + r * 2 + (o - 8)] = acc;
    else if (o < 12) out[10000 + r * 4 + (o - 10) * 2] = acc;
    else             out[10000 + r * 4 + (o - 12) * 2 + 1] = acc;
}

// ============================================================
// launch
// ============================================================
extern "C" void kernel_launch(void* const* d_in, const int* in_sizes, int n_in,
                              void* d_out, int out_size)
{
    const float* fmap0 = (const float*)d_in[0];
    const float* fmap1 = (const float*)d_in[1];
    const float* fmap2 = (const float*)d_in[2];
    const float* fmap3 = (const float*)d_in[3];
    const float* rois  = (const float*)d_in[4];
    const float* w1    = (const float*)d_in[5];
    const float* b1    = (const float*)d_in[6];
    const float* w2    = (const float*)d_in[7];
    const float* b2    = (const float*)d_in[8];
    const float* w_bbox = (const float*)d_in[9];
    const float* b_bbox = (const float*)d_in[10];
    const float* w_cls  = (const float*)d_in[11];
    const float* b_cls  = (const float*)d_in[12];
    const float* w_reg  = (const float*)d_in[13];
    const float* b_reg  = (const float*)d_in[14];
    const float* w_unc  = (const float*)d_in[15];
    const float* b_unc  = (const float*)d_in[16];
    float* out = (float*)d_out;

    float *pT0, *pT1, *pT2, *pT3, *p_pooled, *p_part, *p_x1, *p_x2;
    cudaGetSymbolAddress((void**)&pT0, g_fT0);
    cudaGetSymbolAddress((void**)&pT1, g_fT1);
    cudaGetSymbolAddress((void**)&pT2, g_fT2);
    cudaGetSymbolAddress((void**)&pT3, g_fT3);
    cudaGetSymbolAddress((void**)&p_pooled, g_pooled);
    cudaGetSymbolAddress((void**)&p_part,   g_part);
    cudaGetSymbolAddress((void**)&p_x1,     g_x1);
    cudaGetSymbolAddress((void**)&p_x2,     g_x2);

    // 0. transpose fmaps to channel-last
    {
        dim3 blk(32, 8);
        transpose_kernel<<<dim3(HW0 / 32, NCH / 32, B_), blk>>>(fmap0, pT0, HW0);
        transpose_kernel<<<dim3(HW1 / 32, NCH / 32, B_), blk>>>(fmap1, pT1, HW1);
        transpose_kernel<<<dim3(HW2 / 32, NCH / 32, B_), blk>>>(fmap2, pT2, HW2);
        transpose_kernel<<<dim3(HW3 / 32, NCH / 32, B_), blk>>>(fmap3, pT3, HW3);
    }

    // 1. RoIAlign (coalesced channel-last gathers)
    roi_align_kernel<<<NROIS, NCH>>>(pT0, pT1, pT2, pT3, rois, p_pooled);

    // 2. GEMM1: pooled[1000,9408] x w1[768,9408]^T  (split-K partials)
    {
        dim3 grid((NROIS + 127) / 128, DDIM / 128, SPLITK);
        gemm_nt_splitk<<<grid, 256>>>(p_pooled, w1, p_part, NROIS, DDIM, KDIM);
        reduce_bias_relu<<<(NROIS * DDIM + 255) / 256, 256>>>(p_part, b1, p_x1, NROIS, DDIM);
    }

    // 3. GEMM2: x1[1000,768] x w2[768,768]^T
    {
        dim3 grid((NROIS + 127) / 128, DDIM / 128, SPLITK);
        gemm_nt_splitk<<<grid, 256>>>(p_x1, w2, p_part, NROIS, DDIM, DDIM);
        reduce_bias_relu<<<(NROIS * DDIM + 255) / 256, 256>>>(p_part, b2, p_x2, NROIS, DDIM);
    }

    // 4. heads
    heads_kernel<<<(NROIS * 14 + 255) / 256, 256>>>(
        p_x2, w_bbox, b_bbox, w_cls, b_cls, w_reg, b_reg, w_unc, b_unc, out);
}

// round 12
// speedup vs baseline: 4.2977x; 1.8188x over previous
#include <cuda_runtime.h>
#include <cuda_bf16.h>
#include <math.h>
#include <stdint.h>

#define NROIS 1000
#define NCH   192
#define POOLS 7
#define KDIM  (NCH * POOLS * POOLS)   // 9408
#define DDIM  768
#define SPLITK 6

#define HW0 (128*128)
#define HW1 (64*64)
#define HW2 (32*32)
#define HW3 (16*16)
#define B_  4

// ---- scratch (static device globals; no allocation) ----
__device__ float g_fT0[B_ * HW0 * NCH];
__device__ float g_fT1[B_ * HW1 * NCH];
__device__ float g_fT2[B_ * HW2 * NCH];
__device__ float g_fT3[B_ * HW3 * NCH];
__device__ __nv_bfloat16 g_ahi[NROIS * KDIM];
__device__ __nv_bfloat16 g_alo[NROIS * KDIM];
__device__ __nv_bfloat16 g_w1hi[DDIM * KDIM];
__device__ __nv_bfloat16 g_w1lo[DDIM * KDIM];
__device__ __nv_bfloat16 g_w2hi[DDIM * DDIM];
__device__ __nv_bfloat16 g_w2lo[DDIM * DDIM];
__device__ __nv_bfloat16 g_x1hi[NROIS * DDIM];
__device__ __nv_bfloat16 g_x1lo[NROIS * DDIM];
__device__ float g_part[SPLITK * NROIS * DDIM];
__device__ float g_x2[NROIS * DDIM];

// ============================================================
// PTX helpers
// ============================================================
__device__ __forceinline__ void mma16816(float* c, const uint32_t* a, const uint32_t* b) {
    asm volatile(
        "mma.sync.aligned.m16n8k16.row.col.f32.bf16.bf16.f32 "
        "{%0,%1,%2,%3}, {%4,%5,%6,%7}, {%8,%9}, {%0,%1,%2,%3};\n"
        : "+f"(c[0]), "+f"(c[1]), "+f"(c[2]), "+f"(c[3])
        : "r"(a[0]), "r"(a[1]), "r"(a[2]), "r"(a[3]), "r"(b[0]), "r"(b[1]));
}
__device__ __forceinline__ void ldsm_x4(uint32_t* r, uint32_t addr) {
    asm volatile("ldmatrix.sync.aligned.m8n8.x4.shared.b16 {%0,%1,%2,%3}, [%4];"
                 : "=r"(r[0]), "=r"(r[1]), "=r"(r[2]), "=r"(r[3]) : "r"(addr));
}
__device__ __forceinline__ void ldsm_x2(uint32_t* r, uint32_t addr) {
    asm volatile("ldmatrix.sync.aligned.m8n8.x2.shared.b16 {%0,%1}, [%2];"
                 : "=r"(r[0]), "=r"(r[1]) : "r"(addr));
}
__device__ __forceinline__ void cp_async16(uint32_t dst, const void* src, int srcsize) {
    asm volatile("cp.async.cg.shared.global [%0], [%1], 16, %2;"
                 :: "r"(dst), "l"(src), "r"(srcsize));
}
__device__ __forceinline__ void cp_commit() { asm volatile("cp.async.commit_group;"); }
__device__ __forceinline__ void cp_wait1() { asm volatile("cp.async.wait_group 1;" ::: "memory"); }

// ============================================================
// Kernel 0: transpose [B,C,HW] -> [B,HW,C]
// ============================================================
__global__ void transpose_kernel(const float* __restrict__ in,
                                 float* __restrict__ out, int HW)
{
    __shared__ float tile[32][33];
    const int p0 = blockIdx.x * 32;
    const int c0 = blockIdx.y * 32;
    const int b  = blockIdx.z;
    const int tx = threadIdx.x, ty = threadIdx.y;
    #pragma unroll
    for (int j = 0; j < 4; j++) {
        const int c = c0 + ty + j * 8;
        tile[ty + j * 8][tx] = in[((size_t)b * NCH + c) * HW + p0 + tx];
    }
    __syncthreads();
    #pragma unroll
    for (int j = 0; j < 4; j++) {
        const int p = p0 + ty + j * 8;
        out[((size_t)b * HW + p) * NCH + c0 + tx] = tile[tx][ty + j * 8];
    }
}

// ============================================================
// Kernel 0b: split fp32 -> bf16 hi/lo
// ============================================================
__global__ void split_bf16(const float* __restrict__ w,
                           __nv_bfloat16* __restrict__ hi,
                           __nv_bfloat16* __restrict__ lo, int n)
{
    int i = blockIdx.x * blockDim.x + threadIdx.x;
    if (i < n) {
        float v = w[i];
        __nv_bfloat16 h = __float2bfloat16(v);
        hi[i] = h;
        lo[i] = __float2bfloat16(v - __bfloat162float(h));
    }
}

// ============================================================
// Kernel 1: pyramid RoIAlign -> bf16 hi/lo [NROIS, 9408]
// ============================================================
__global__ void roi_align_kernel(const float* __restrict__ fT0,
                                 const float* __restrict__ fT1,
                                 const float* __restrict__ fT2,
                                 const float* __restrict__ fT3,
                                 const float* __restrict__ rois,
                                 __nv_bfloat16* __restrict__ ahi,
                                 __nv_bfloat16* __restrict__ alo)
{
    const int r = blockIdx.x;
    const int tid = threadIdx.x;

    __shared__ int   sIdx[196][4];
    __shared__ float sW[196][4];
    __shared__ float sBuf[NCH * 49];

    const float* roi = rois + r * 5;
    const float by1 = roi[0], bx1 = roi[1], by2 = roi[2], bx2 = roi[3];
    const int bix = (int)roi[4];

    const float h = by2 - by1;
    const float w = bx2 - bx1;
    const float area = h * w;
    int lvl;
    if (area > 0.0f) {
        float lv = 4.0f + 0.5f * log2f(area);
        lvl = (int)rintf(lv);
        lvl = max(0, min(3, lvl));
    } else lvl = 0;

    const float* fm;
    int H;
    if      (lvl == 0) { fm = fT0; H = 128; }
    else if (lvl == 1) { fm = fT1; H = 64;  }
    else if (lvl == 2) { fm = fT2; H = 32;  }
    else               { fm = fT3; H = 16;  }
    const int W = H;
    const float Hs = (float)H;

    const float y1s = by1 * Hs, x1s = bx1 * Hs;
    const float y2s = by2 * Hs, x2s = bx2 * Hs;
    const float bin_h = fmaxf(y2s - y1s, 1.0f) * (1.0f / (float)POOLS);
    const float bin_w = fmaxf(x2s - x1s, 1.0f) * (1.0f / (float)POOLS);

    for (int s = tid; s < 196; s += blockDim.x) {
        const int jy = s / 14, jx = s % 14;
        const float gy = (float)(jy >> 1) + 0.25f + (float)(jy & 1) * 0.5f;
        const float gx = (float)(jx >> 1) + 0.25f + (float)(jx & 1) * 0.5f;
        float y = y1s + gy * bin_h;
        float x = x1s + gx * bin_w;
        const bool valid = (y >= -1.0f) && (y <= Hs) && (x >= -1.0f) && (x <= Hs);
        y = fminf(fmaxf(y, 0.0f), Hs - 1.0f);
        x = fminf(fmaxf(x, 0.0f), Hs - 1.0f);
        const float yf = floorf(y), xf = floorf(x);
        const int y0 = (int)yf, x0 = (int)xf;
        const int y1i = min(y0 + 1, H - 1);
        const int x1i = min(x0 + 1, W - 1);
        const float ly = y - yf, lx = x - xf;
        const float v = valid ? 1.0f : 0.0f;
        sIdx[s][0] = (y0 * W + x0) * NCH;
        sIdx[s][1] = (y0 * W + x1i) * NCH;
        sIdx[s][2] = (y1i * W + x0) * NCH;
        sIdx[s][3] = (y1i * W + x1i) * NCH;
        sW[s][0] = (1.0f - ly) * (1.0f - lx) * v;
        sW[s][1] = (1.0f - ly) * lx * v;
        sW[s][2] = ly * (1.0f - lx) * v;
        sW[s][3] = ly * lx * v;
    }
    __syncthreads();

    const int c = tid;  // 0..191
    const float* base = fm + (size_t)bix * (H * W) * NCH + c;
    #pragma unroll
    for (int ph = 0; ph < 7; ph++) {
        for (int pw = 0; pw < 7; pw++) {
            float acc = 0.0f;
            #pragma unroll
            for (int sy = 0; sy < 2; sy++) {
                #pragma unroll
                for (int sx = 0; sx < 2; sx++) {
                    const int s = (ph * 2 + sy) * 14 + (pw * 2 + sx);
                    acc += sW[s][0] * __ldg(base + sIdx[s][0])
                         + sW[s][1] * __ldg(base + sIdx[s][1])
                         + sW[s][2] * __ldg(base + sIdx[s][2])
                         + sW[s][3] * __ldg(base + sIdx[s][3]);
                }
            }
            sBuf[c * 49 + ph * 7 + pw] = acc * 0.25f;
        }
    }
    __syncthreads();

    __nv_bfloat16* ohi = ahi + (size_t)r * KDIM;
    __nv_bfloat16* olo = alo + (size_t)r * KDIM;
    for (int i = tid; i < KDIM; i += NCH) {
        float v = sBuf[i];
        __nv_bfloat16 hh = __float2bfloat16(v);
        ohi[i] = hh;
        olo[i] = __float2bfloat16(v - __bfloat162float(hh));
    }
}

// ============================================================
// Kernel 2: bf16 split-K tensor-core GEMM:  part[z] = A * B^T slice
//  A[M,K] (hi/lo), B[N,K] (hi/lo), acc = AhBh + AhBl + AlBh
//  BM=128, BN=256, BK=32, 512 threads, warp tile 64x32
//  grid (M/128, N/256, SPLITK), dynamic smem 96KB
// ============================================================
__global__ void __launch_bounds__(512)
gemm_bf16_splitk(const __nv_bfloat16* __restrict__ Ahi, const __nv_bfloat16* __restrict__ Alo,
                 const __nv_bfloat16* __restrict__ Bhi, const __nv_bfloat16* __restrict__ Blo,
                 float* __restrict__ part, int M, int N, int K)
{
    extern __shared__ char smem_raw[];
    const uint32_t sbase = (uint32_t)__cvta_generic_to_shared(smem_raw);
    // layout (bytes): Ahi[2][8192] | Alo[2][8192] | Bhi[2][16384] | Blo[2][16384]
    const uint32_t sAhi = sbase;
    const uint32_t sBhi = sbase + 32768;

    const int t = threadIdx.x;
    const int bm = blockIdx.x * 128;
    const int bn = blockIdx.y * 256;
    const int Ks = K / SPLITK;
    const int k0 = blockIdx.z * Ks;
    const int iters = Ks / 32;

    // ---- gmem->smem mapping (cp.async 16B each) ----
    const int arow = t >> 2, achk = t & 3;
    const bool avalid = (bm + arow) < M;
    const size_t aoff = (size_t)(bm + arow) * K + k0 + achk * 8;
    const uint32_t sa_off = arow * 64 + (((achk ^ ((arow >> 1) & 3))) << 4);
    const int brow0 = t >> 2,          bchk0 = t & 3;
    const int brow1 = (t + 512) >> 2,  bchk1 = t & 3;
    const size_t boff0 = (size_t)(bn + brow0) * K + k0 + bchk0 * 8;
    const size_t boff1 = (size_t)(bn + brow1) * K + k0 + bchk1 * 8;
    const uint32_t sb_off0 = brow0 * 64 + ((bchk0 ^ ((brow0 >> 1) & 3)) << 4);
    const uint32_t sb_off1 = brow1 * 64 + ((bchk1 ^ ((brow1 >> 1) & 3)) << 4);

    // ---- compute-side addressing ----
    const int wid = t >> 5, lane = t & 31;
    const int wm = wid & 1, wn = wid >> 1;      // 2 x 8 warp grid
    const int qa = lane >> 3;
    const int ra = (qa & 1) * 8 + (lane & 7);
    const int ca = qa >> 1;
    int a_term[4], a_swz[4];
    #pragma unroll
    for (int mt = 0; mt < 4; mt++) {
        int row = wm * 64 + mt * 16 + ra;
        a_term[mt] = row * 64;
        a_swz[mt] = (row >> 1) & 3;
    }
    const int lb = lane & 15;
    const int rb = lb & 7, cb = lb >> 3;
    int b_term[4], b_swz[4];
    #pragma unroll
    for (int nt = 0; nt < 4; nt++) {
        int row = wn * 32 + nt * 8 + rb;
        b_term[nt] = row * 64;
        b_swz[nt] = (row >> 1) & 3;
    }

    float acc[4][4][4];
    #pragma unroll
    for (int i = 0; i < 4; i++)
        #pragma unroll
        for (int j = 0; j < 4; j++)
            #pragma unroll
            for (int q = 0; q < 4; q++) acc[i][j][q] = 0.0f;

    // ---- prologue: stage 0 ----
    {
        const int ki = 0;
        cp_async16(sAhi + sa_off, Ahi + aoff + ki, avalid ? 16 : 0);
        cp_async16(sAhi + 16384 + sa_off, Alo + aoff + ki, avalid ? 16 : 0);
        cp_async16(sBhi + sb_off0, Bhi + boff0 + ki, 16);
        cp_async16(sBhi + sb_off1, Bhi + boff1 + ki, 16);
        cp_async16(sBhi + 32768 + sb_off0, Blo + boff0 + ki, 16);
        cp_async16(sBhi + 32768 + sb_off1, Blo + boff1 + ki, 16);
    }
    cp_commit();

    for (int it = 0; it < iters; it++) {
        if (it + 1 < iters) {
            const int ki = (it + 1) * 32;
            const uint32_t as = ((it + 1) & 1) * 8192;
            const uint32_t bs = ((it + 1) & 1) * 16384;
            cp_async16(sAhi + as + sa_off, Ahi + aoff + ki, avalid ? 16 : 0);
            cp_async16(sAhi + 16384 + as + sa_off, Alo + aoff + ki, avalid ? 16 : 0);
            cp_async16(sBhi + bs + sb_off0, Bhi + boff0 + ki, 16);
            cp_async16(sBhi + bs + sb_off1, Bhi + boff1 + ki, 16);
            cp_async16(sBhi + 32768 + bs + sb_off0, Blo + boff0 + ki, 16);
            cp_async16(sBhi + 32768 + bs + sb_off1, Blo + boff1 + ki, 16);
        }
        cp_commit();
        cp_wait1();
        __syncthreads();

        const uint32_t as = (it & 1) * 8192;
        const uint32_t bs = (it & 1) * 16384;
        #pragma unroll
        for (int hh = 0; hh < 2; hh++) {
            uint32_t bhf[4][2], blf[4][2];
            #pragma unroll
            for (int nt = 0; nt < 4; nt++) {
                uint32_t addr = sBhi + bs + b_term[nt] + ((((hh << 1) + cb) ^ b_swz[nt]) << 4);
                ldsm_x2(bhf[nt], addr);
                ldsm_x2(blf[nt], addr + 32768);
            }
            #pragma unroll
            for (int mt = 0; mt < 4; mt++) {
                uint32_t ahf[4], alf[4];
                uint32_t addr = sAhi + as + a_term[mt] + ((((hh << 1) + ca) ^ a_swz[mt]) << 4);
                ldsm_x4(ahf, addr);
                ldsm_x4(alf, addr + 16384);
                #pragma unroll
                for (int nt = 0; nt < 4; nt++) {
                    mma16816(acc[mt][nt], ahf, bhf[nt]);
                    mma16816(acc[mt][nt], ahf, blf[nt]);
                    mma16816(acc[mt][nt], alf, bhf[nt]);
                }
            }
        }
        __syncthreads();
    }

    // ---- epilogue: write fp32 partials ----
    const int g = lane >> 2, tg = lane & 3;
    float* Cp = part + (size_t)blockIdx.z * M * N;
    #pragma unroll
    for (int mt = 0; mt < 4; mt++) {
        #pragma unroll
        for (int nt = 0; nt < 4; nt++) {
            const int row = bm + wm * 64 + mt * 16 + g;
            const int col = bn + wn * 32 + nt * 8 + tg * 2;
            if (row < M)
                *(float2*)&Cp[(size_t)row * N + col] = make_float2(acc[mt][nt][0], acc[mt][nt][1]);
            if (row + 8 < M)
                *(float2*)&Cp[(size_t)(row + 8) * N + col] = make_float2(acc[mt][nt][2], acc[mt][nt][3]);
        }
    }
}

// ============================================================
// Kernel 3a: reduce partials + bias + relu -> bf16 hi/lo
// ============================================================
__global__ void reduce_bias_relu_bf16(const float* __restrict__ part,
                                      const float* __restrict__ bias,
                                      __nv_bfloat16* __restrict__ ohi,
                                      __nv_bfloat16* __restrict__ olo,
                                      int M, int N)
{
    const int i = blockIdx.x * blockDim.x + threadIdx.x;
    if (i < M * N) {
        float s = bias[i % N];
        #pragma unroll
        for (int kz = 0; kz < SPLITK; kz++)
            s += part[(size_t)kz * M * N + i];
        s = fmaxf(s, 0.0f);
        __nv_bfloat16 hh = __float2bfloat16(s);
        ohi[i] = hh;
        olo[i] = __float2bfloat16(s - __bfloat162float(hh));
    }
}

// Kernel 3b: reduce partials + bias + relu -> fp32
__global__ void reduce_bias_relu_f32(const float* __restrict__ part,
                                     const float* __restrict__ bias,
                                     float* __restrict__ out, int M, int N)
{
    const int i = blockIdx.x * blockDim.x + threadIdx.x;
    if (i < M * N) {
        float s = bias[i % N];
        #pragma unroll
        for (int kz = 0; kz < SPLITK; kz++)
            s += part[(size_t)kz * M * N + i];
        out[i] = fmaxf(s, 0.0f);
    }
}

// ============================================================
// Kernel 4: heads
// ============================================================
__global__ void heads_kernel(const float* __restrict__ x,
                             const float* __restrict__ wb, const float* __restrict__ bb,
                             const float* __restrict__ wc, const float* __restrict__ bc,
                             const float* __restrict__ wr, const float* __restrict__ br,
                             const float* __restrict__ wu, const float* __restrict__ bu,
                             float* __restrict__ out)
{
    const int gg = blockIdx.x * blockDim.x + threadIdx.x;
    if (gg >= NROIS * 14) return;
    const int r = gg / 14;
    const int o = gg % 14;

    const float* wrow;
    float acc;
    if (o < 8)       { wrow = wb + o * DDIM;        acc = bb[o]; }
    else if (o < 10) { wrow = wc + (o - 8) * DDIM;  acc = bc[o - 8]; }
    else if (o < 12) { wrow = wr + (o - 10) * DDIM; acc = br[o - 10]; }
    else             { wrow = wu + (o - 12) * DDIM; acc = bu[o - 12]; }

    const float* xr = x + (size_t)r * DDIM;
    #pragma unroll 4
    for (int k = 0; k < DDIM; k += 4) {
        float4 xv = *(const float4*)(xr + k);
        float4 wv = __ldg((const float4*)(wrow + k));
        acc = fmaf(xv.x, wv.x, acc);
        acc = fmaf(xv.y, wv.y, acc);
        acc = fmaf(xv.z, wv.z, acc);
        acc = fmaf(xv.w, wv.w, acc);
    }

    if (o < 8)       out[r * 8 + o] = acc;
    else if (o < 10) out[8000 + r * 2 + (o - 8)] = acc;
    else if (o < 12) out[10000 + r * 4 + (o - 10) * 2] = acc;
    else             out[10000 + r * 4 + (o - 12) * 2 + 1] = acc;
}

// ============================================================
// launch
// ============================================================
extern "C" void kernel_launch(void* const* d_in, const int* in_sizes, int n_in,
                              void* d_out, int out_size)
{
    const float* fmap0 = (const float*)d_in[0];
    const float* fmap1 = (const float*)d_in[1];
    const float* fmap2 = (const float*)d_in[2];
    const float* fmap3 = (const float*)d_in[3];
    const float* rois  = (const float*)d_in[4];
    const float* w1    = (const float*)d_in[5];
    const float* b1    = (const float*)d_in[6];
    const float* w2    = (const float*)d_in[7];
    const float* b2    = (const float*)d_in[8];
    const float* w_bbox = (const float*)d_in[9];
    const float* b_bbox = (const float*)d_in[10];
    const float* w_cls  = (const float*)d_in[11];
    const float* b_cls  = (const float*)d_in[12];
    const float* w_reg  = (const float*)d_in[13];
    const float* b_reg  = (const float*)d_in[14];
    const float* w_unc  = (const float*)d_in[15];
    const float* b_unc  = (const float*)d_in[16];
    float* out = (float*)d_out;

    float *pT0, *pT1, *pT2, *pT3, *p_part, *p_x2;
    __nv_bfloat16 *p_ahi, *p_alo, *p_w1hi, *p_w1lo, *p_w2hi, *p_w2lo, *p_x1hi, *p_x1lo;
    cudaGetSymbolAddress((void**)&pT0, g_fT0);
    cudaGetSymbolAddress((void**)&pT1, g_fT1);
    cudaGetSymbolAddress((void**)&pT2, g_fT2);
    cudaGetSymbolAddress((void**)&pT3, g_fT3);
    cudaGetSymbolAddress((void**)&p_ahi, g_ahi);
    cudaGetSymbolAddress((void**)&p_alo, g_alo);
    cudaGetSymbolAddress((void**)&p_w1hi, g_w1hi);
    cudaGetSymbolAddress((void**)&p_w1lo, g_w1lo);
    cudaGetSymbolAddress((void**)&p_w2hi, g_w2hi);
    cudaGetSymbolAddress((void**)&p_w2lo, g_w2lo);
    cudaGetSymbolAddress((void**)&p_x1hi, g_x1hi);
    cudaGetSymbolAddress((void**)&p_x1lo, g_x1lo);
    cudaGetSymbolAddress((void**)&p_part, g_part);
    cudaGetSymbolAddress((void**)&p_x2,   g_x2);

    cudaFuncSetAttribute(gemm_bf16_splitk,
                         cudaFuncAttributeMaxDynamicSharedMemorySize, 98304);

    // 0. transposes + weight splits
    {
        dim3 blk(32, 8);
        transpose_kernel<<<dim3(HW0 / 32, NCH / 32, B_), blk>>>(fmap0, pT0, HW0);
        transpose_kernel<<<dim3(HW1 / 32, NCH / 32, B_), blk>>>(fmap1, pT1, HW1);
        transpose_kernel<<<dim3(HW2 / 32, NCH / 32, B_), blk>>>(fmap2, pT2, HW2);
        transpose_kernel<<<dim3(HW3 / 32, NCH / 32, B_), blk>>>(fmap3, pT3, HW3);
        split_bf16<<<(DDIM * KDIM + 255) / 256, 256>>>(w1, p_w1hi, p_w1lo, DDIM * KDIM);
        split_bf16<<<(DDIM * DDIM + 255) / 256, 256>>>(w2, p_w2hi, p_w2lo, DDIM * DDIM);
    }

    // 1. RoIAlign -> bf16 hi/lo activations
    roi_align_kernel<<<NROIS, NCH>>>(pT0, pT1, pT2, pT3, rois, p_ahi, p_alo);

    // 2. GEMM1: [1000,9408] x [768,9408]^T
    {
        dim3 grid((NROIS + 127) / 128, DDIM / 256, SPLITK);
        gemm_bf16_splitk<<<grid, 512, 98304>>>(p_ahi, p_alo, p_w1hi, p_w1lo,
                                               p_part, NROIS, DDIM, KDIM);
        reduce_bias_relu_bf16<<<(NROIS * DDIM + 255) / 256, 256>>>(
            p_part, b1, p_x1hi, p_x1lo, NROIS, DDIM);
    }

    // 3. GEMM2: [1000,768] x [768,768]^T
    {
        dim3 grid((NROIS + 127) / 128, DDIM / 256, SPLITK);
        gemm_bf16_splitk<<<grid, 512, 98304>>>(p_x1hi, p_x1lo, p_w2hi, p_w2lo,
                                               p_part, NROIS, DDIM, DDIM);
        reduce_bias_relu_f32<<<(NROIS * DDIM + 255) / 256, 256>>>(
            p_part, b2, p_x2, NROIS, DDIM);
    }

    // 4. heads
    heads_kernel<<<(NROIS * 14 + 255) / 256, 256>>>(
        p_x2, w_bbox, b_bbox, w_cls, b_cls, w_reg, b_reg, w_unc, b_unc, out);
}